// round 4
// baseline (speedup 1.0000x reference)
#include <cuda_runtime.h>

#define CC 173
#define LL 400
#define BB 64
#define NSPLIT 346   // mlp1 split-K blocks (2 per channel, K-chunk 160)

// Static scratch (no allocations allowed).
__device__ float g_pooled[BB * CC * 32 * 10];      // [B][55360] pooled features
__device__ float g_hpart[NSPLIT * BB * 128];       // split-K partials

#define UNPACK2(lo, hi, v) \
    asm("mov.b64 {%0, %1}, %2;" : "=f"(lo), "=f"(hi) : "l"(v))
#define FMA2(d, a, b, c) \
    asm("fma.rn.f32x2 %0, %1, %2, %3;" : "=l"(d) : "l"(a), "l"(b), "l"(c))

// Dynamic smem layout (bytes)
#define W2P_OFF   0                     // float2 [32][113] (w,w) pairs, stride 113 (odd -> conflict-free LDS.64)
#define Z_OFF     28928                 // float2 [16][10*27]  z[f1][win*27+i] = (v_i, v_{i+20})
#define XS_OFF    63488                 // float [408]
#define W1S_OFF   65120                 // float [144]
#define A1S_OFF   65696                 // float [16]
#define B1S_OFF   65760                 // float [16]
#define A2S_OFF   65824                 // float [32]
#define B2S_OFF   65952                 // float [32]
#define PMAX_OFF  66080                 // float [20][32]
#define SMEM_BYTES 68640

// ---------------------------------------------------------------------------
// Fused per-(b,c) tower, 640 threads (20 warps -> balanced 5/5/5/5 per SMSP):
// conv1(1->16,k9,p4)+BN+ReLU -> paired z array -> conv2 via FFMA2 -> BN+ReLU
// -> maxpool(40) -> g_pooled
// ---------------------------------------------------------------------------
__global__ __launch_bounds__(640, 1) void tower_kernel(
    const float* __restrict__ x,
    const float* __restrict__ w1, const float* __restrict__ b1,
    const float* __restrict__ g1, const float* __restrict__ be1,
    const float* __restrict__ m1, const float* __restrict__ v1,
    const float* __restrict__ w2, const float* __restrict__ b2,
    const float* __restrict__ g2, const float* __restrict__ be2,
    const float* __restrict__ m2, const float* __restrict__ v2)
{
    extern __shared__ char smem[];
    float2* w2p = (float2*)(smem + W2P_OFF);
    float*  zf  = (float*)(smem + Z_OFF);       // scalar view of z for stage-1 writes
    float*  xs  = (float*)(smem + XS_OFF);
    float*  w1s = (float*)(smem + W1S_OFF);
    float*  A1s = (float*)(smem + A1S_OFF);
    float*  B1s = (float*)(smem + B1S_OFF);
    float*  A2s = (float*)(smem + A2S_OFF);
    float*  B2s = (float*)(smem + B2S_OFF);
    float*  pmax = (float*)(smem + PMAX_OFF);

    const int b = blockIdx.x;
    const int c = blockIdx.y;
    const int tid = threadIdx.x;

    // ---- stage 0: loads ----
    if (tid < 408) {
        int p = tid - 4;
        xs[tid] = (p >= 0 && p < LL) ? x[(b * CC + c) * LL + p] : 0.f;
    }
    for (int i = tid; i < 144; i += 640) w1s[i] = w1[c * 144 + i];
    for (int i = tid; i < 3584; i += 640) {
        float w = w2[c * 3584 + i];
        int f2 = i / 112, t = i % 112;
        w2p[f2 * 113 + t] = make_float2(w, w);
    }
    if (tid >= 512 && tid < 528) {
        int f = tid - 512;
        int cf = c * 16 + f;
        float inv = g1[cf] * rsqrtf(v1[cf] + 1e-5f);
        A1s[f] = inv;
        B1s[f] = fmaf(b1[cf] - m1[cf], inv, be1[cf]);
    } else if (tid >= 544 && tid < 576) {
        int f = tid - 544;
        int cf = c * 32 + f;
        float inv = g2[cf] * rsqrtf(v2[cf] + 1e-5f);
        A2s[f] = inv;
        B2s[f] = fmaf(b2[cf] - m2[cf], inv, be2[cf]);
    }
    __syncthreads();

    // ---- stage 1: conv1 + BN + ReLU, written straight into paired z ----
    // v_idx (window-tap vector) = y1 at output position idx-3, idx in 0..407.
    // z slot (f, win, i): .x = v_{win*40+i} (i<=26), .y = v_{win*40+i+20}
    for (int it = tid; it < 16 * 408; it += 640) {
        const int f = it / 408, idx = it % 408;
        const int p = idx - 3;
        float val = 0.f;
        if (p >= 0 && p < LL) {
            float s = 0.f;
            const float* wf = &w1s[f * 9];
            const float* xp = &xs[p];
            #pragma unroll
            for (int k = 0; k < 9; k++) s = fmaf(xp[k], wf[k], s);
            val = fmaxf(fmaf(s, A1s[f], B1s[f]), 0.f);
        }
        const int win1 = idx / 40, r = idx % 40;
        const int fb = f * 270;
        if (r <= 26 && win1 <= 9) zf[2 * (fb + win1 * 27 + r)] = val;
        if (r >= 20 && win1 <= 9) zf[2 * (fb + win1 * 27 + r - 20) + 1] = val;
        if (r <= 6 && win1 >= 1)  zf[2 * (fb + (win1 - 1) * 27 + r + 20) + 1] = val;
    }
    __syncthreads();

    // ---- stage 2: conv2 (FFMA2) + BN + ReLU + maxpool(40) ----
    // warp w: win = w/2, lhalf = w%2 (warp-uniform -> broadcast z LDS.64),
    // lane = f2. acc2[l] packs outputs (l0+l, l0+l+20), l0 = lhalf*10.
    {
        const int w    = tid >> 5;
        const int lane = tid & 31;
        const int win  = w >> 1;
        const int lhalf = w & 1;
        const int l0   = lhalf * 10;

        unsigned long long acc2[10];
        #pragma unroll
        for (int l = 0; l < 10; l++) acc2[l] = 0ull;

        const unsigned long long* w2u = (const unsigned long long*)(smem + W2P_OFF);
        const unsigned long long* zu  = (const unsigned long long*)(smem + Z_OFF);

        for (int f1 = 0; f1 < 16; f1++) {
            const unsigned long long* wp = w2u + lane * 113 + f1 * 7;
            const unsigned long long wk0 = wp[0], wk1 = wp[1], wk2 = wp[2],
                                     wk3 = wp[3], wk4 = wp[4], wk5 = wp[5], wk6 = wp[6];
            const unsigned long long* zb = zu + f1 * 270 + win * 27 + l0;
            unsigned long long P0 = zb[0], P1 = zb[1], P2 = zb[2], P3 = zb[3],
                               P4 = zb[4], P5 = zb[5], P6 = zb[6];
            #pragma unroll
            for (int l = 0; l < 10; l++) {
                unsigned long long a = acc2[l];
                FMA2(a, P0, wk0, a);
                FMA2(a, P1, wk1, a);
                FMA2(a, P2, wk2, a);
                FMA2(a, P3, wk3, a);
                FMA2(a, P4, wk4, a);
                FMA2(a, P5, wk5, a);
                FMA2(a, P6, wk6, a);
                acc2[l] = a;
                P0 = P1; P1 = P2; P2 = P3; P3 = P4; P4 = P5; P5 = P6;
                P6 = zb[l + 7];           // max local index 16 <= 26
            }
        }
        const float sA = A2s[lane], sB = B2s[lane];
        float mx = -3.402823466e38f;
        #pragma unroll
        for (int l = 0; l < 10; l++) {
            float lo, hi;
            UNPACK2(lo, hi, acc2[l]);
            mx = fmaxf(mx, fmaf(lo, sA, sB));
            mx = fmaxf(mx, fmaf(hi, sA, sB));
        }
        pmax[w * 32 + lane] = mx;   // partial over this lhalf's 20 positions
    }
    __syncthreads();

    // combine the two lhalf partials, relu, write out
    for (int i = tid; i < 320; i += 640) {
        const int wi = i >> 5, f2 = i & 31;
        float m = fmaxf(fmaxf(pmax[(wi * 2) * 32 + f2], pmax[(wi * 2 + 1) * 32 + f2]), 0.f);
        g_pooled[b * 55360 + (c * 32 + f2) * 10 + wi] = m;
    }
}

// ---------------------------------------------------------------------------
// MLP layer 1, deterministic split-K (K-chunk 160, 2 blocks per channel).
// k-tile 32, float4 global loads.
// ---------------------------------------------------------------------------
__global__ __launch_bounds__(256, 2) void mlp1_kernel(const float* __restrict__ wc1)
{
    __shared__ float As[64][33];
    __shared__ float Bs[128][33];
    const int blk  = blockIdx.x;          // 0..345
    const int base = blk * 160;
    const int t  = threadIdx.x;
    const int tb = t & 15;                // 16 b-groups x 4 rows
    const int tj = t >> 4;                // 16 j-groups x 8 cols

    float acc[4][8];
    #pragma unroll
    for (int i = 0; i < 4; i++)
        #pragma unroll
        for (int j = 0; j < 8; j++) acc[i][j] = 0.f;

    for (int k0 = 0; k0 < 160; k0 += 32) {
        #pragma unroll
        for (int r = 0; r < 2; r++) {
            int idx = t + 256 * r;                  // 0..511 = 64 rows x 8 float4
            int row = idx >> 3, seg = idx & 7;
            float4 v = *(const float4*)&g_pooled[row * 55360 + base + k0 + seg * 4];
            As[row][seg * 4 + 0] = v.x; As[row][seg * 4 + 1] = v.y;
            As[row][seg * 4 + 2] = v.z; As[row][seg * 4 + 3] = v.w;
        }
        #pragma unroll
        for (int r = 0; r < 4; r++) {
            int idx = t + 256 * r;                  // 0..1023 = 128 rows x 8 float4
            int row = idx >> 3, seg = idx & 7;
            float4 v = *(const float4*)&wc1[row * 55360 + base + k0 + seg * 4];
            Bs[row][seg * 4 + 0] = v.x; Bs[row][seg * 4 + 1] = v.y;
            Bs[row][seg * 4 + 2] = v.z; Bs[row][seg * 4 + 3] = v.w;
        }
        __syncthreads();
        #pragma unroll
        for (int kk = 0; kk < 32; kk++) {
            float a[4], wv[8];
            #pragma unroll
            for (int i = 0; i < 4; i++) a[i] = As[tb * 4 + i][kk];
            #pragma unroll
            for (int j = 0; j < 8; j++) wv[j] = Bs[tj * 8 + j][kk];
            #pragma unroll
            for (int i = 0; i < 4; i++)
                #pragma unroll
                for (int j = 0; j < 8; j++) acc[i][j] = fmaf(a[i], wv[j], acc[i][j]);
        }
        __syncthreads();
    }
    #pragma unroll
    for (int i = 0; i < 4; i++)
        #pragma unroll
        for (int j = 0; j < 8; j++)
            g_hpart[blk * 8192 + (tb * 4 + i) * 128 + (tj * 8 + j)] = acc[i][j];
}

// ---------------------------------------------------------------------------
// Reduce split-K partials, ReLU, second linear, write out[b].
// ---------------------------------------------------------------------------
__global__ __launch_bounds__(128) void mlp2_kernel(
    const float* __restrict__ bc1, const float* __restrict__ wc2,
    const float* __restrict__ bc2, float* __restrict__ out)
{
    const int b = blockIdx.x;
    const int j = threadIdx.x;
    float s = 0.f;
    for (int sb = 0; sb < NSPLIT; sb++) s += g_hpart[sb * 8192 + b * 128 + j];
    float h = fmaxf(s + bc1[j], 0.f);
    float p = h * wc2[j];
    __shared__ float red[128];
    red[j] = p;
    __syncthreads();
    for (int o = 64; o > 0; o >>= 1) {
        if (j < o) red[j] += red[j + o];
        __syncthreads();
    }
    if (j == 0) out[b] = red[0] + bc2[0];
}

// ---------------------------------------------------------------------------
extern "C" void kernel_launch(void* const* d_in, const int* in_sizes, int n_in,
                              void* d_out, int out_size)
{
    const float* x    = (const float*)d_in[0];
    const float* w1   = (const float*)d_in[1];
    const float* b1   = (const float*)d_in[2];
    const float* g1   = (const float*)d_in[3];
    const float* be1  = (const float*)d_in[4];
    const float* m1   = (const float*)d_in[5];
    const float* v1   = (const float*)d_in[6];
    const float* w2   = (const float*)d_in[7];
    const float* b2   = (const float*)d_in[8];
    const float* g2   = (const float*)d_in[9];
    const float* be2  = (const float*)d_in[10];
    const float* m2   = (const float*)d_in[11];
    const float* v2   = (const float*)d_in[12];
    const float* wc1  = (const float*)d_in[13];
    const float* bc1  = (const float*)d_in[14];
    const float* wc2  = (const float*)d_in[15];
    const float* bc2  = (const float*)d_in[16];
    float* out = (float*)d_out;

    cudaFuncSetAttribute(tower_kernel,
                         cudaFuncAttributeMaxDynamicSharedMemorySize, SMEM_BYTES);

    dim3 gridA(BB, CC);   // consecutive bids share c -> w2 stays L2-hot
    tower_kernel<<<gridA, 640, SMEM_BYTES>>>(x, w1, b1, g1, be1, m1, v1,
                                             w2, b2, g2, be2, m2, v2);
    mlp1_kernel<<<NSPLIT, 256>>>(wc1);
    mlp2_kernel<<<BB, 128>>>(bc1, wc2, bc2, out);
}